// round 6
// baseline (speedup 1.0000x reference)
#include <cuda_runtime.h>
#include <cuda_fp16.h>
#include <cstdint>
#include <type_traits>

// ---------------- problem constants ----------------
#define B_      16
#define Q_      300
#define DMODEL  256
#define NHEADS  8
#define HD      32
#define LV      8400          // 80*80 + 40*40 + 20*20
#define BQ      (B_*Q_)       // 4800
#define MV      (B_*LV)       // 134400 rows of value
#define MT_PAD  4864          // 38*128

// ---------------- scratch (device globals; zero-initialized) ----------------
__device__ __half g_v16[MV * DMODEL];        // projected value, fp16
__device__ __half g_tmp16[MT_PAD * DMODEL];  // sampled heads, fp16; rows>=4800 stay 0
__device__ __half g_wv16[DMODEL * DMODEL];   // Wv  in fp16
__device__ __half g_wo16[DMODEL * DMODEL];   // Wout in fp16
__device__ float  g_off[BQ * 192];
__device__ float  g_attn[BQ * 96];

// ---------------- helpers ----------------
__device__ __forceinline__ uint32_t smem_u32(const void* p) {
    uint32_t a;
    asm("{ .reg .u64 t; cvta.to.shared.u64 t, %1; cvt.u32.u64 %0, t; }" : "=r"(a) : "l"(p));
    return a;
}
__device__ __forceinline__ void ldsm_x4(uint32_t* r, uint32_t addr) {
    asm volatile("ldmatrix.sync.aligned.m8n8.x4.shared.b16 {%0,%1,%2,%3}, [%4];"
                 : "=r"(r[0]), "=r"(r[1]), "=r"(r[2]), "=r"(r[3]) : "r"(addr));
}
__device__ __forceinline__ void ldsm_x4_t(uint32_t* r, uint32_t addr) {
    asm volatile("ldmatrix.sync.aligned.m8n8.x4.trans.shared.b16 {%0,%1,%2,%3}, [%4];"
                 : "=r"(r[0]), "=r"(r[1]), "=r"(r[2]), "=r"(r[3]) : "r"(addr));
}
__device__ __forceinline__ void mma16(float* c, const uint32_t* a, const uint32_t* b) {
    asm volatile(
        "mma.sync.aligned.m16n8k16.row.col.f32.f16.f16.f32 "
        "{%0,%1,%2,%3}, {%4,%5,%6,%7}, {%8,%9}, {%0,%1,%2,%3};\n"
        : "+f"(c[0]), "+f"(c[1]), "+f"(c[2]), "+f"(c[3])
        : "r"(a[0]), "r"(a[1]), "r"(a[2]), "r"(a[3]), "r"(b[0]), "r"(b[1]));
}
__device__ __forceinline__ uint32_t packh2(float x, float y) {
    __half2 h = __floats2half2_rn(x, y);
    return *reinterpret_cast<uint32_t*>(&h);
}

// ---------------- fp16 GEMM geometry ----------------
#define BK       32
#define ASTR     40    // halves per A smem row
#define BSTR     264   // halves per B smem row
#define A_HALVES (128 * ASTR)          // 5120
#define B_HALVES (32 * BSTR)           // 8448
#define SM_A0    0
#define SM_A1    (A_HALVES)
#define SM_B0    (2 * A_HALVES)
#define SM_B1    (2 * A_HALVES + B_HALVES)
#define SM_TOT_H (2 * A_HALVES + 2 * B_HALVES)       // 27136 halves
#define SM_TOT_B (SM_TOT_H * 2)                      // 54272 bytes
#define EPI_STR  72
#define EPI_HALVES 1152

// ============================================================================
// fp32 -> fp16 convert (for Wv / Wout), n multiple of 4
// ============================================================================
__global__ void cvt_fp16(const float* __restrict__ src, __half* __restrict__ dst, int n) {
    int i = (blockIdx.x * blockDim.x + threadIdx.x) * 4;
    if (i < n) {
        float4 v = *reinterpret_cast<const float4*>(src + i);
        uint2 u = make_uint2(packh2(v.x, v.y), packh2(v.z, v.w));
        *reinterpret_cast<uint2*>(dst + i) = u;
    }
}

// ============================================================================
// fp16 tensor-core GEMM: C[M x 256] = A[M x 256] @ W16[256 x 256] + bias.
// ============================================================================
template<typename TA, typename TC>
__global__ void __launch_bounds__(256, 1)
gemm_fp16(const TA* __restrict__ A, const __half* __restrict__ W16,
          const float* __restrict__ bias, TC* __restrict__ C, int Mstore) {
    extern __shared__ __half sh[];
    const uint32_t sb = smem_u32(sh);
    const int tid = threadIdx.x, warp = tid >> 5, lane = tid & 31;
    const int wm = warp >> 2, wn = warp & 3;
    const int g = lane >> 2, tg = lane & 3;
    const int m0 = blockIdx.x * 128;

    const int arow = tid >> 1, ac0 = (tid & 1) * 16;
    const int brow = tid >> 3, bc0 = (tid & 7) * 32;

    float acc[4][8][4];
    #pragma unroll
    for (int i = 0; i < 4; i++)
        #pragma unroll
        for (int j = 0; j < 8; j++)
            #pragma unroll
            for (int k = 0; k < 4; k++) acc[i][j][k] = 0.f;

    // ---- prologue: fill stage 0 ----
    {
        if constexpr (std::is_same_v<TA, float>) {
            const float* ap = A + (size_t)(m0 + arow) * 256 + ac0;
            #pragma unroll
            for (int i = 0; i < 4; i++) {
                float4 v = *reinterpret_cast<const float4*>(ap + 4 * i);
                uint2 u = make_uint2(packh2(v.x, v.y), packh2(v.z, v.w));
                *reinterpret_cast<uint2*>(&sh[SM_A0 + arow * ASTR + ac0 + 4 * i]) = u;
            }
        } else {
            const __half* ap = A + (size_t)(m0 + arow) * 256 + ac0;
            #pragma unroll
            for (int i = 0; i < 2; i++)
                *reinterpret_cast<uint4*>(&sh[SM_A0 + arow * ASTR + ac0 + 8 * i]) =
                    *reinterpret_cast<const uint4*>(ap + 8 * i);
        }
        const __half* wp = W16 + (size_t)brow * 256 + bc0;
        #pragma unroll
        for (int i = 0; i < 4; i++)
            *reinterpret_cast<uint4*>(&sh[SM_B0 + brow * BSTR + bc0 + 8 * i]) =
                *reinterpret_cast<const uint4*>(wp + 8 * i);
    }
    __syncthreads();

    const uint32_t a_lrow = (uint32_t)(lane & 15);
    const uint32_t a_kadd = (uint32_t)(lane >> 4) * 8;

    #pragma unroll
    for (int c = 0; c < 8; c++) {
        const int cur = c & 1;
        float4 raf[4]; uint4 rah[2]; uint4 rb[4];
        if (c < 7) {
            const int kc = (c + 1) * BK;
            if constexpr (std::is_same_v<TA, float>) {
                const float* ap = A + (size_t)(m0 + arow) * 256 + kc + ac0;
                #pragma unroll
                for (int i = 0; i < 4; i++)
                    raf[i] = *reinterpret_cast<const float4*>(ap + 4 * i);
            } else {
                const __half* ap = A + (size_t)(m0 + arow) * 256 + kc + ac0;
                #pragma unroll
                for (int i = 0; i < 2; i++)
                    rah[i] = *reinterpret_cast<const uint4*>(ap + 8 * i);
            }
            const __half* wp = W16 + (size_t)(kc + brow) * 256 + bc0;
            #pragma unroll
            for (int i = 0; i < 4; i++)
                rb[i] = *reinterpret_cast<const uint4*>(wp + 8 * i);
        }

        const uint32_t aB = sb + (cur ? SM_A1 : SM_A0) * 2;
        const uint32_t bB = sb + (cur ? SM_B1 : SM_B0) * 2;
        #pragma unroll
        for (int k16 = 0; k16 < 2; k16++) {
            uint32_t af[4][4], bf[8][2];
            #pragma unroll
            for (int mi = 0; mi < 4; mi++) {
                uint32_t addr = aB + ((wm * 64 + mi * 16 + a_lrow) * ASTR
                                      + k16 * 16 + a_kadd) * 2;
                ldsm_x4(af[mi], addr);
            }
            #pragma unroll
            for (int nq = 0; nq < 4; nq++) {
                uint32_t r[4];
                uint32_t addr = bB + ((k16 * 16 + a_lrow) * BSTR
                                      + wn * 64 + nq * 16 + a_kadd) * 2;
                ldsm_x4_t(r, addr);
                bf[2 * nq][0] = r[0]; bf[2 * nq][1] = r[1];
                bf[2 * nq + 1][0] = r[2]; bf[2 * nq + 1][1] = r[3];
            }
            #pragma unroll
            for (int mi = 0; mi < 4; mi++)
                #pragma unroll
                for (int ni = 0; ni < 8; ni++)
                    mma16(acc[mi][ni], af[mi], bf[ni]);
        }

        if (c < 7) {
            const int nxt = (c + 1) & 1;
            __half* dA = &sh[(nxt ? SM_A1 : SM_A0)];
            __half* dB = &sh[(nxt ? SM_B1 : SM_B0)];
            if constexpr (std::is_same_v<TA, float>) {
                #pragma unroll
                for (int i = 0; i < 4; i++) {
                    uint2 u = make_uint2(packh2(raf[i].x, raf[i].y), packh2(raf[i].z, raf[i].w));
                    *reinterpret_cast<uint2*>(&dA[arow * ASTR + ac0 + 4 * i]) = u;
                }
            } else {
                #pragma unroll
                for (int i = 0; i < 2; i++)
                    *reinterpret_cast<uint4*>(&dA[arow * ASTR + ac0 + 8 * i]) = rah[i];
            }
            #pragma unroll
            for (int i = 0; i < 4; i++)
                *reinterpret_cast<uint4*>(&dB[brow * BSTR + bc0 + 8 * i]) = rb[i];
            __syncthreads();
        }
    }

    // ---- epilogue ----
    float2 bb[8];
    #pragma unroll
    for (int ni = 0; ni < 8; ni++)
        bb[ni] = *reinterpret_cast<const float2*>(&bias[wn * 64 + ni * 8 + 2 * tg]);

    if constexpr (std::is_same_v<TC, __half>) {
        __syncthreads();
        __half* buf = &sh[warp * EPI_HALVES];
        #pragma unroll
        for (int mi = 0; mi < 4; mi++) {
            #pragma unroll
            for (int ni = 0; ni < 8; ni++) {
                const int cc = ni * 8 + 2 * tg;
                __half2 lo = __floats2half2_rn(acc[mi][ni][0] + bb[ni].x,
                                               acc[mi][ni][1] + bb[ni].y);
                __half2 hi = __floats2half2_rn(acc[mi][ni][2] + bb[ni].x,
                                               acc[mi][ni][3] + bb[ni].y);
                *reinterpret_cast<__half2*>(&buf[g * EPI_STR + cc]) = lo;
                *reinterpret_cast<__half2*>(&buf[(g + 8) * EPI_STR + cc]) = hi;
            }
            __syncwarp();
            #pragma unroll
            for (int p = 0; p < 4; p++) {
                const int row = p * 4 + (lane >> 3);
                const int ch  = lane & 7;
                uint4 v = *reinterpret_cast<const uint4*>(&buf[row * EPI_STR + ch * 8]);
                const int grow = m0 + wm * 64 + mi * 16 + row;
                if (grow < Mstore)
                    *reinterpret_cast<uint4*>(
                        &C[(size_t)grow * 256 + wn * 64 + ch * 8]) = v;
            }
            __syncwarp();
        }
    } else {
        #pragma unroll
        for (int mi = 0; mi < 4; mi++) {
            const int r0 = m0 + wm * 64 + mi * 16 + g;
            const int r1 = r0 + 8;
            #pragma unroll
            for (int ni = 0; ni < 8; ni++) {
                const int cc = wn * 64 + ni * 8 + 2 * tg;
                if (r0 < Mstore)
                    *reinterpret_cast<float2*>(&C[(size_t)r0 * 256 + cc]) =
                        make_float2(acc[mi][ni][0] + bb[ni].x, acc[mi][ni][1] + bb[ni].y);
                if (r1 < Mstore)
                    *reinterpret_cast<float2*>(&C[(size_t)r1 * 256 + cc]) =
                        make_float2(acc[mi][ni][2] + bb[ni].x, acc[mi][ni][3] + bb[ni].y);
            }
        }
    }
}

// ============================================================================
// Exact fp32 GEMM, 32x64 tile (offsets). grid (N/64, 4800/32) = 450 blocks.
// ============================================================================
__global__ __launch_bounds__(256, 6)
void fgemm32x64(const float* __restrict__ A, const float* __restrict__ Bm,
                const float* __restrict__ bias, float* __restrict__ C, int N) {
    __shared__ float As[32 * 36];
    __shared__ float Bs[32 * 68];
    const int tid = threadIdx.x;
    const int n0 = blockIdx.x * 64;
    const int m0 = blockIdx.y * 32;
    const int ty = tid >> 4, tx = tid & 15;          // 2 rows, 4 cols per thread
    const int arow = tid >> 3, acol = (tid & 7) * 4;
    const int brow = tid >> 3, bcol = (tid & 7) * 8;

    float acc[2][4] = {};
    for (int kc = 0; kc < 256; kc += 32) {
        *reinterpret_cast<float4*>(&As[arow * 36 + acol]) =
            *reinterpret_cast<const float4*>(A + (size_t)(m0 + arow) * 256 + kc + acol);
        #pragma unroll
        for (int i = 0; i < 2; i++)
            *reinterpret_cast<float4*>(&Bs[brow * 68 + bcol + 4 * i]) =
                *reinterpret_cast<const float4*>(Bm + (size_t)(kc + brow) * N + n0 + bcol + 4 * i);
        __syncthreads();
        #pragma unroll
        for (int kk = 0; kk < 32; kk++) {
            const float a0 = As[(ty * 2 + 0) * 36 + kk];
            const float a1 = As[(ty * 2 + 1) * 36 + kk];
            const float4 bv = *reinterpret_cast<const float4*>(&Bs[kk * 68 + tx * 4]);
            acc[0][0] += a0 * bv.x; acc[0][1] += a0 * bv.y; acc[0][2] += a0 * bv.z; acc[0][3] += a0 * bv.w;
            acc[1][0] += a1 * bv.x; acc[1][1] += a1 * bv.y; acc[1][2] += a1 * bv.z; acc[1][3] += a1 * bv.w;
        }
        __syncthreads();
    }
    const float4 bv = *reinterpret_cast<const float4*>(&bias[n0 + tx * 4]);
    #pragma unroll
    for (int i = 0; i < 2; i++) {
        float4 v = make_float4(acc[i][0] + bv.x, acc[i][1] + bv.y,
                               acc[i][2] + bv.z, acc[i][3] + bv.w);
        *reinterpret_cast<float4*>(&C[(size_t)(m0 + ty * 2 + i) * N + n0 + tx * 4]) = v;
    }
}

// ============================================================================
// Exact fp32 GEMM, 32x32 tile (attn logits). grid (N/32, 4800/32) = 450 blocks.
// ============================================================================
__global__ __launch_bounds__(256, 6)
void fgemm32x32(const float* __restrict__ A, const float* __restrict__ Bm,
                const float* __restrict__ bias, float* __restrict__ C, int N) {
    __shared__ float As[32 * 36];
    __shared__ float Bs[32 * 36];
    const int tid = threadIdx.x;
    const int n0 = blockIdx.x * 32;
    const int m0 = blockIdx.y * 32;
    const int ty = tid >> 4, tx = tid & 15;          // 2 rows, 2 cols per thread
    const int arow = tid >> 3, acol = (tid & 7) * 4;

    float acc[2][2] = {};
    for (int kc = 0; kc < 256; kc += 32) {
        *reinterpret_cast<float4*>(&As[arow * 36 + acol]) =
            *reinterpret_cast<const float4*>(A + (size_t)(m0 + arow) * 256 + kc + acol);
        *reinterpret_cast<float4*>(&Bs[arow * 36 + acol]) =
            *reinterpret_cast<const float4*>(Bm + (size_t)(kc + arow) * N + n0 + acol);
        __syncthreads();
        #pragma unroll
        for (int kk = 0; kk < 32; kk++) {
            const float a0 = As[(ty * 2 + 0) * 36 + kk];
            const float a1 = As[(ty * 2 + 1) * 36 + kk];
            const float2 bv = *reinterpret_cast<const float2*>(&Bs[kk * 36 + tx * 2]);
            acc[0][0] += a0 * bv.x;  acc[0][1] += a0 * bv.y;
            acc[1][0] += a1 * bv.x;  acc[1][1] += a1 * bv.y;
        }
        __syncthreads();
    }
    const float b0 = bias[n0 + tx * 2], b1 = bias[n0 + tx * 2 + 1];
    #pragma unroll
    for (int i = 0; i < 2; i++) {
        float2 v = make_float2(acc[i][0] + b0, acc[i][1] + b1);
        *reinterpret_cast<float2*>(&C[(size_t)(m0 + ty * 2 + i) * N + n0 + tx * 2]) = v;
    }
}

// ============================================================================
// Deformable sampling: owner-lane precompute + fp16 gathers.
// ============================================================================
__global__ __launch_bounds__(256)
void sample_kernel(const float* __restrict__ off, const float* __restrict__ attn,
                   const float* __restrict__ rp, const __half* __restrict__ v,
                   __half* __restrict__ tmp) {
    const int bq   = blockIdx.x;
    const int h    = threadIdx.x >> 5;
    const int lane = threadIdx.x & 31;
    const int b    = bq / Q_;

    const float refx = rp[bq * 4 + 0];
    const float refy = rp[bq * 4 + 1];

    float logit = -1e30f, px = 0.f, py = 0.f;
    int W = 1, start = 0;
    if (lane < 12) {
        logit = attn[bq * 96 + h * 12 + lane];
        const float ox = off[bq * 192 + h * 24 + lane * 2 + 0];
        const float oy = off[bq * 192 + h * 24 + lane * 2 + 1];
        const int lvl = lane >> 2;
        W     = (lvl == 0) ? 80 : ((lvl == 1) ? 40 : 20);
        start = (lvl == 0) ? 0 : ((lvl == 1) ? 6400 : 8000);
        const float Wf = (float)W;
        const float ptsx = fminf(fmaxf(refx + ox, 0.f), 1.f);
        const float ptsy = fminf(fmaxf(refy + oy, 0.f), 1.f);
        px = ptsx * Wf - 0.5f;
        py = ptsy * Wf - 0.5f;
    }
    float mx = logit;
    #pragma unroll
    for (int s = 16; s > 0; s >>= 1) mx = fmaxf(mx, __shfl_xor_sync(0xffffffffu, mx, s));
    float e = (lane < 12) ? expf(logit - mx) : 0.f;
    float ssum = e;
    #pragma unroll
    for (int s = 16; s > 0; s >>= 1) ssum += __shfl_xor_sync(0xffffffffu, ssum, s);
    const float wgt = e / ssum;

    int i00 = 0, i01 = 0, i10 = 0, i11 = 0;
    float w00 = 0.f, w01 = 0.f, w10 = 0.f, w11 = 0.f;
    if (lane < 12) {
        const float x0f = floorf(px), y0f = floorf(py);
        const float fx = px - x0f, fy = py - y0f;
        const int x0 = (int)x0f, y0 = (int)y0f;
        const int x1 = x0 + 1, y1 = y0 + 1;
        const bool vx0 = (unsigned)x0 < (unsigned)W, vx1 = (unsigned)x1 < (unsigned)W;
        const bool vy0 = (unsigned)y0 < (unsigned)W, vy1 = (unsigned)y1 < (unsigned)W;
        const int x0c = min(max(x0, 0), W - 1), x1c = min(max(x1, 0), W - 1);
        const int y0c = min(max(y0, 0), W - 1), y1c = min(max(y1, 0), W - 1);
        i00 = start + y0c * W + x0c;  i01 = start + y0c * W + x1c;
        i10 = start + y1c * W + x0c;  i11 = start + y1c * W + x1c;
        w00 = wgt * (1.f - fx) * (1.f - fy) * (float)(vx0 && vy0);
        w01 = wgt * fx * (1.f - fy) * (float)(vx1 && vy0);
        w10 = wgt * (1.f - fx) * fy * (float)(vx0 && vy1);
        w11 = wgt * fx * fy * (float)(vx1 && vy1);
    }

    const __half* vb = v + (size_t)b * LV * DMODEL + h * HD + lane;
    float acc = 0.f;
    #pragma unroll
    for (int j = 0; j < 12; j++) {
        const int   a00 = __shfl_sync(0xffffffffu, i00, j);
        const int   a01 = __shfl_sync(0xffffffffu, i01, j);
        const int   a10 = __shfl_sync(0xffffffffu, i10, j);
        const int   a11 = __shfl_sync(0xffffffffu, i11, j);
        const float q00 = __shfl_sync(0xffffffffu, w00, j);
        const float q01 = __shfl_sync(0xffffffffu, w01, j);
        const float q10 = __shfl_sync(0xffffffffu, w10, j);
        const float q11 = __shfl_sync(0xffffffffu, w11, j);
        acc += q00 * __half2float(vb[(size_t)a00 * DMODEL]);
        acc += q01 * __half2float(vb[(size_t)a01 * DMODEL]);
        acc += q10 * __half2float(vb[(size_t)a10 * DMODEL]);
        acc += q11 * __half2float(vb[(size_t)a11 * DMODEL]);
    }

    tmp[(size_t)bq * DMODEL + h * HD + lane] = __float2half(acc);
}

// ============================================================================
extern "C" void kernel_launch(void* const* d_in, const int* in_sizes, int n_in,
                              void* d_out, int out_size) {
    const float* query = (const float*)d_in[0];
    const float* rp    = (const float*)d_in[1];
    const float* value = (const float*)d_in[2];
    const float* Wv    = (const float*)d_in[3];
    const float* bv    = (const float*)d_in[4];
    const float* Woff  = (const float*)d_in[5];
    const float* boff  = (const float*)d_in[6];
    const float* Wattn = (const float*)d_in[7];
    const float* battn = (const float*)d_in[8];
    const float* Wout  = (const float*)d_in[9];
    const float* bout  = (const float*)d_in[10];
    float* out = (float*)d_out;

    __half *pv16, *ptmp16, *pwv16, *pwo16;
    float *poff, *pattn;
    cudaGetSymbolAddress((void**)&pv16,   g_v16);
    cudaGetSymbolAddress((void**)&ptmp16, g_tmp16);
    cudaGetSymbolAddress((void**)&pwv16,  g_wv16);
    cudaGetSymbolAddress((void**)&pwo16,  g_wo16);
    cudaGetSymbolAddress((void**)&poff,   g_off);
    cudaGetSymbolAddress((void**)&pattn,  g_attn);

    static cudaStream_t s1 = nullptr;
    static cudaEvent_t ev0 = nullptr, ev1 = nullptr;
    if (s1 == nullptr) {
        cudaStreamCreateWithFlags(&s1, cudaStreamNonBlocking);
        cudaEventCreateWithFlags(&ev0, cudaEventDisableTiming);
        cudaEventCreateWithFlags(&ev1, cudaEventDisableTiming);
        cudaFuncSetAttribute(gemm_fp16<float, __half>,
                             cudaFuncAttributeMaxDynamicSharedMemorySize, SM_TOT_B);
        cudaFuncSetAttribute(gemm_fp16<__half, float>,
                             cudaFuncAttributeMaxDynamicSharedMemorySize, SM_TOT_B);
    }

    // ---- fork: value-projection chain on s1, query chain on default ----
    cudaEventRecord(ev0, 0);
    cudaStreamWaitEvent(s1, ev0, 0);

    // s1: Wv -> fp16, then v = value @ Wv + bv  (fp16 TC, coalesced fp16 stores)
    cvt_fp16<<<64, 256, 0, s1>>>(Wv, pwv16, DMODEL * DMODEL);
    gemm_fp16<float, __half><<<MV / 128, 256, SM_TOT_B, s1>>>(value, pwv16, bv, pv16, MV);
    cudaEventRecord(ev1, s1);

    // default: offsets / attn logits (exact fp32, 450-CTA tiles) + Wout cvt
    fgemm32x64<<<dim3(3, BQ / 32), 256>>>(query, Woff, boff, poff, 192);
    fgemm32x32<<<dim3(3, BQ / 32), 256>>>(query, Wattn, battn, pattn, 96);
    cvt_fp16<<<64, 256>>>(Wout, pwo16, DMODEL * DMODEL);

    // join, then sampling + output GEMM
    cudaStreamWaitEvent(0, ev1, 0);
    sample_kernel<<<BQ, 256>>>(poff, pattn, rp, pv16, ptmp16);
    gemm_fp16<__half, float><<<MT_PAD / 128, 256, SM_TOT_B>>>(ptmp16, pwo16, bout, out, BQ);
}

// round 7
// speedup vs baseline: 1.1461x; 1.1461x over previous
#include <cuda_runtime.h>
#include <cuda_fp16.h>
#include <cstdint>
#include <type_traits>

// ---------------- problem constants ----------------
#define B_      16
#define Q_      300
#define DMODEL  256
#define NHEADS  8
#define HD      32
#define LV      8400          // 80*80 + 40*40 + 20*20
#define BQ      (B_*Q_)       // 4800
#define MV      (B_*LV)       // 134400 rows of value
#define MT_PAD  4864          // 38*128

// ---------------- scratch (device globals; zero-initialized) ----------------
__device__ __half g_v16[MV * DMODEL];        // projected value, fp16
__device__ __half g_tmp16[MT_PAD * DMODEL];  // sampled heads, fp16; rows>=4800 stay 0
__device__ __half g_wv16[DMODEL * DMODEL];   // Wv  in fp16
__device__ __half g_wo16[DMODEL * DMODEL];   // Wout in fp16
__device__ float  g_off[BQ * 192];
__device__ float  g_attn[BQ * 96];

// ---------------- helpers ----------------
__device__ __forceinline__ uint32_t smem_u32(const void* p) {
    uint32_t a;
    asm("{ .reg .u64 t; cvta.to.shared.u64 t, %1; cvt.u32.u64 %0, t; }" : "=r"(a) : "l"(p));
    return a;
}
__device__ __forceinline__ void ldsm_x4(uint32_t* r, uint32_t addr) {
    asm volatile("ldmatrix.sync.aligned.m8n8.x4.shared.b16 {%0,%1,%2,%3}, [%4];"
                 : "=r"(r[0]), "=r"(r[1]), "=r"(r[2]), "=r"(r[3]) : "r"(addr));
}
__device__ __forceinline__ void ldsm_x4_t(uint32_t* r, uint32_t addr) {
    asm volatile("ldmatrix.sync.aligned.m8n8.x4.trans.shared.b16 {%0,%1,%2,%3}, [%4];"
                 : "=r"(r[0]), "=r"(r[1]), "=r"(r[2]), "=r"(r[3]) : "r"(addr));
}
__device__ __forceinline__ void mma16(float* c, const uint32_t* a, const uint32_t* b) {
    asm volatile(
        "mma.sync.aligned.m16n8k16.row.col.f32.f16.f16.f32 "
        "{%0,%1,%2,%3}, {%4,%5,%6,%7}, {%8,%9}, {%0,%1,%2,%3};\n"
        : "+f"(c[0]), "+f"(c[1]), "+f"(c[2]), "+f"(c[3])
        : "r"(a[0]), "r"(a[1]), "r"(a[2]), "r"(a[3]), "r"(b[0]), "r"(b[1]));
}
__device__ __forceinline__ uint32_t packh2(float x, float y) {
    __half2 h = __floats2half2_rn(x, y);
    return *reinterpret_cast<uint32_t*>(&h);
}

// ---------------- fp16 GEMM geometry (block 128x128, 2 CTAs/SM) ----------------
#define BK       32
#define ASTR     40    // halves per A smem row (32 + 8 pad)
#define BSTR     136   // halves per B smem row (128 + 8 pad)
#define A_HALVES (128 * ASTR)          // 5120
#define B_HALVES (32 * BSTR)           // 4352
#define SM_A0    0
#define SM_A1    (A_HALVES)
#define SM_B0    (2 * A_HALVES)
#define SM_B1    (2 * A_HALVES + B_HALVES)
#define SM_TOT_H (2 * A_HALVES + 2 * B_HALVES)       // 18944 halves
#define SM_TOT_B (SM_TOT_H * 2)                      // 37888 bytes
#define EPI_STR  72
#define EPI_HALVES 1152                              // 8 warps * 1152 = 9216 <= SM_TOT_H

// ============================================================================
// fp32 -> fp16 convert for BOTH weight matrices in one launch (n each = 65536)
// ============================================================================
__global__ void cvt2_fp16(const float* __restrict__ s0, __half* __restrict__ d0,
                          const float* __restrict__ s1, __half* __restrict__ d1) {
    int i = (blockIdx.x * blockDim.x + threadIdx.x) * 4;
    const float* s = (i < DMODEL * DMODEL) ? s0 : s1;
    __half* d      = (i < DMODEL * DMODEL) ? d0 : d1;
    int j = (i < DMODEL * DMODEL) ? i : i - DMODEL * DMODEL;
    float4 v = *reinterpret_cast<const float4*>(s + j);
    uint2 u = make_uint2(packh2(v.x, v.y), packh2(v.z, v.w));
    *reinterpret_cast<uint2*>(d + j) = u;
}

// ============================================================================
// fp16 tensor-core GEMM: C[M x 256] = A[M x 256] @ W16[256 x 256] + bias.
// Block 128(m) x 128(n); grid (Mtiles, 2). 8 warps as 4(m) x 2(n), warp 32x64.
// 2 CTAs/SM co-resident (acc = 64 regs). Double-buffered, reg-staged prefetch.
// ============================================================================
template<typename TA, typename TC>
__global__ void __launch_bounds__(256, 2)
gemm_fp16(const TA* __restrict__ A, const __half* __restrict__ W16,
          const float* __restrict__ bias, TC* __restrict__ C, int Mstore) {
    extern __shared__ __half sh[];
    const uint32_t sb = smem_u32(sh);
    const int tid = threadIdx.x, warp = tid >> 5, lane = tid & 31;
    const int wm = warp >> 1, wn = warp & 1;         // 4(m) x 2(n)
    const int g = lane >> 2, tg = lane & 3;
    const int m0 = blockIdx.x * 128;
    const int n0 = blockIdx.y * 128;

    const int arow = tid >> 1, ac0 = (tid & 1) * 16;   // A: 16 elems / thread
    const int brow = tid >> 3, bc0 = (tid & 7) * 16;   // B: 16 halves / thread

    float acc[2][8][4];
    #pragma unroll
    for (int i = 0; i < 2; i++)
        #pragma unroll
        for (int j = 0; j < 8; j++)
            #pragma unroll
            for (int k = 0; k < 4; k++) acc[i][j][k] = 0.f;

    // ---- prologue: fill stage 0 ----
    {
        if constexpr (std::is_same_v<TA, float>) {
            const float* ap = A + (size_t)(m0 + arow) * 256 + ac0;
            #pragma unroll
            for (int i = 0; i < 4; i++) {
                float4 v = *reinterpret_cast<const float4*>(ap + 4 * i);
                uint2 u = make_uint2(packh2(v.x, v.y), packh2(v.z, v.w));
                *reinterpret_cast<uint2*>(&sh[SM_A0 + arow * ASTR + ac0 + 4 * i]) = u;
            }
        } else {
            const __half* ap = A + (size_t)(m0 + arow) * 256 + ac0;
            #pragma unroll
            for (int i = 0; i < 2; i++)
                *reinterpret_cast<uint4*>(&sh[SM_A0 + arow * ASTR + ac0 + 8 * i]) =
                    *reinterpret_cast<const uint4*>(ap + 8 * i);
        }
        const __half* wp = W16 + (size_t)brow * 256 + n0 + bc0;
        #pragma unroll
        for (int i = 0; i < 2; i++)
            *reinterpret_cast<uint4*>(&sh[SM_B0 + brow * BSTR + bc0 + 8 * i]) =
                *reinterpret_cast<const uint4*>(wp + 8 * i);
    }
    __syncthreads();

    const uint32_t a_lrow = (uint32_t)(lane & 15);
    const uint32_t a_kadd = (uint32_t)(lane >> 4) * 8;

    #pragma unroll
    for (int c = 0; c < 8; c++) {
        const int cur = c & 1;
        float4 raf[4]; uint4 rah[2]; uint4 rb[2];
        if (c < 7) {
            const int kc = (c + 1) * BK;
            if constexpr (std::is_same_v<TA, float>) {
                const float* ap = A + (size_t)(m0 + arow) * 256 + kc + ac0;
                #pragma unroll
                for (int i = 0; i < 4; i++)
                    raf[i] = *reinterpret_cast<const float4*>(ap + 4 * i);
            } else {
                const __half* ap = A + (size_t)(m0 + arow) * 256 + kc + ac0;
                #pragma unroll
                for (int i = 0; i < 2; i++)
                    rah[i] = *reinterpret_cast<const uint4*>(ap + 8 * i);
            }
            const __half* wp = W16 + (size_t)(kc + brow) * 256 + n0 + bc0;
            #pragma unroll
            for (int i = 0; i < 2; i++)
                rb[i] = *reinterpret_cast<const uint4*>(wp + 8 * i);
        }

        // ---- compute current stage ----
        const uint32_t aB = sb + (cur ? SM_A1 : SM_A0) * 2;
        const uint32_t bB = sb + (cur ? SM_B1 : SM_B0) * 2;
        #pragma unroll
        for (int k16 = 0; k16 < 2; k16++) {
            uint32_t af[2][4], bf[8][2];
            #pragma unroll
            for (int mi = 0; mi < 2; mi++) {
                uint32_t addr = aB + ((wm * 32 + mi * 16 + a_lrow) * ASTR
                                      + k16 * 16 + a_kadd) * 2;
                ldsm_x4(af[mi], addr);
            }
            #pragma unroll
            for (int nq = 0; nq < 4; nq++) {
                uint32_t r[4];
                uint32_t addr = bB + ((k16 * 16 + a_lrow) * BSTR
                                      + wn * 64 + nq * 16 + a_kadd) * 2;
                ldsm_x4_t(r, addr);
                bf[2 * nq][0] = r[0]; bf[2 * nq][1] = r[1];
                bf[2 * nq + 1][0] = r[2]; bf[2 * nq + 1][1] = r[3];
            }
            #pragma unroll
            for (int mi = 0; mi < 2; mi++)
                #pragma unroll
                for (int ni = 0; ni < 8; ni++)
                    mma16(acc[mi][ni], af[mi], bf[ni]);
        }

        if (c < 7) {
            const int nxt = (c + 1) & 1;
            __half* dA = &sh[(nxt ? SM_A1 : SM_A0)];
            __half* dB = &sh[(nxt ? SM_B1 : SM_B0)];
            if constexpr (std::is_same_v<TA, float>) {
                #pragma unroll
                for (int i = 0; i < 4; i++) {
                    uint2 u = make_uint2(packh2(raf[i].x, raf[i].y), packh2(raf[i].z, raf[i].w));
                    *reinterpret_cast<uint2*>(&dA[arow * ASTR + ac0 + 4 * i]) = u;
                }
            } else {
                #pragma unroll
                for (int i = 0; i < 2; i++)
                    *reinterpret_cast<uint4*>(&dA[arow * ASTR + ac0 + 8 * i]) = rah[i];
            }
            #pragma unroll
            for (int i = 0; i < 2; i++)
                *reinterpret_cast<uint4*>(&dB[brow * BSTR + bc0 + 8 * i]) = rb[i];
            __syncthreads();
        }
    }

    // ---- epilogue ----
    float2 bb[8];
    #pragma unroll
    for (int ni = 0; ni < 8; ni++)
        bb[ni] = *reinterpret_cast<const float2*>(&bias[n0 + wn * 64 + ni * 8 + 2 * tg]);

    if constexpr (std::is_same_v<TC, __half>) {
        __syncthreads();                   // MMA smem reads done; reuse smem for repack
        __half* buf = &sh[warp * EPI_HALVES];
        #pragma unroll
        for (int mi = 0; mi < 2; mi++) {
            #pragma unroll
            for (int ni = 0; ni < 8; ni++) {
                const int cc = ni * 8 + 2 * tg;
                __half2 lo = __floats2half2_rn(acc[mi][ni][0] + bb[ni].x,
                                               acc[mi][ni][1] + bb[ni].y);
                __half2 hi = __floats2half2_rn(acc[mi][ni][2] + bb[ni].x,
                                               acc[mi][ni][3] + bb[ni].y);
                *reinterpret_cast<__half2*>(&buf[g * EPI_STR + cc]) = lo;
                *reinterpret_cast<__half2*>(&buf[(g + 8) * EPI_STR + cc]) = hi;
            }
            __syncwarp();
            #pragma unroll
            for (int p = 0; p < 4; p++) {
                const int row = p * 4 + (lane >> 3);
                const int ch  = lane & 7;
                uint4 v = *reinterpret_cast<const uint4*>(&buf[row * EPI_STR + ch * 8]);
                const int grow = m0 + wm * 32 + mi * 16 + row;
                if (grow < Mstore)
                    *reinterpret_cast<uint4*>(
                        &C[(size_t)grow * 256 + n0 + wn * 64 + ch * 8]) = v;
            }
            __syncwarp();
        }
    } else {
        #pragma unroll
        for (int mi = 0; mi < 2; mi++) {
            const int r0 = m0 + wm * 32 + mi * 16 + g;
            const int r1 = r0 + 8;
            #pragma unroll
            for (int ni = 0; ni < 8; ni++) {
                const int cc = n0 + wn * 64 + ni * 8 + 2 * tg;
                if (r0 < Mstore)
                    *reinterpret_cast<float2*>(&C[(size_t)r0 * 256 + cc]) =
                        make_float2(acc[mi][ni][0] + bb[ni].x, acc[mi][ni][1] + bb[ni].y);
                if (r1 < Mstore)
                    *reinterpret_cast<float2*>(&C[(size_t)r1 * 256 + cc]) =
                        make_float2(acc[mi][ni][2] + bb[ni].x, acc[mi][ni][3] + bb[ni].y);
            }
        }
    }
}

// ============================================================================
// Fused exact fp32 GEMM for offsets + attn logits (concat N = 192 + 96).
// Tile 32x32; grid (9, 150). blockIdx.x 0..5 -> Woff/g_off, 6..8 -> Wattn/g_attn.
// ============================================================================
__global__ __launch_bounds__(256, 6)
void fgemm_qfused(const float* __restrict__ A,
                  const float* __restrict__ Woff, const float* __restrict__ boff,
                  const float* __restrict__ Wattn, const float* __restrict__ battn,
                  float* __restrict__ Coff, float* __restrict__ Cattn) {
    __shared__ float As[32 * 36];
    __shared__ float Bs[32 * 36];
    const int tid = threadIdx.x;
    const int bx = blockIdx.x;
    const int m0 = blockIdx.y * 32;

    const float* Bm; const float* bias; float* C; int N; int n0;
    if (bx < 6) { Bm = Woff;  bias = boff;  C = Coff;  N = 192; n0 = bx * 32; }
    else        { Bm = Wattn; bias = battn; C = Cattn; N = 96;  n0 = (bx - 6) * 32; }

    const int ty = tid >> 4, tx = tid & 15;          // 2 rows, 2 cols per thread
    const int arow = tid >> 3, acol = (tid & 7) * 4;

    float acc[2][2] = {};
    for (int kc = 0; kc < 256; kc += 32) {
        *reinterpret_cast<float4*>(&As[arow * 36 + acol]) =
            *reinterpret_cast<const float4*>(A + (size_t)(m0 + arow) * 256 + kc + acol);
        *reinterpret_cast<float4*>(&Bs[arow * 36 + acol]) =
            *reinterpret_cast<const float4*>(Bm + (size_t)(kc + arow) * N + n0 + acol);
        __syncthreads();
        #pragma unroll
        for (int kk = 0; kk < 32; kk++) {
            const float a0 = As[(ty * 2 + 0) * 36 + kk];
            const float a1 = As[(ty * 2 + 1) * 36 + kk];
            const float2 bv = *reinterpret_cast<const float2*>(&Bs[kk * 36 + tx * 2]);
            acc[0][0] += a0 * bv.x;  acc[0][1] += a0 * bv.y;
            acc[1][0] += a1 * bv.x;  acc[1][1] += a1 * bv.y;
        }
        __syncthreads();
    }
    const float b0 = bias[n0 + tx * 2], b1 = bias[n0 + tx * 2 + 1];
    #pragma unroll
    for (int i = 0; i < 2; i++) {
        float2 v = make_float2(acc[i][0] + b0, acc[i][1] + b1);
        *reinterpret_cast<float2*>(&C[(size_t)(m0 + ty * 2 + i) * N + n0 + tx * 2]) = v;
    }
}

// ============================================================================
// Deformable sampling: owner-lane precompute + fp16 gathers.
// ============================================================================
__global__ __launch_bounds__(256)
void sample_kernel(const float* __restrict__ off, const float* __restrict__ attn,
                   const float* __restrict__ rp, const __half* __restrict__ v,
                   __half* __restrict__ tmp) {
    const int bq   = blockIdx.x;
    const int h    = threadIdx.x >> 5;
    const int lane = threadIdx.x & 31;
    const int b    = bq / Q_;

    const float refx = rp[bq * 4 + 0];
    const float refy = rp[bq * 4 + 1];

    float logit = -1e30f, px = 0.f, py = 0.f;
    int W = 1, start = 0;
    if (lane < 12) {
        logit = attn[bq * 96 + h * 12 + lane];
        const float ox = off[bq * 192 + h * 24 + lane * 2 + 0];
        const float oy = off[bq * 192 + h * 24 + lane * 2 + 1];
        const int lvl = lane >> 2;
        W     = (lvl == 0) ? 80 : ((lvl == 1) ? 40 : 20);
        start = (lvl == 0) ? 0 : ((lvl == 1) ? 6400 : 8000);
        const float Wf = (float)W;
        const float ptsx = fminf(fmaxf(refx + ox, 0.f), 1.f);
        const float ptsy = fminf(fmaxf(refy + oy, 0.f), 1.f);
        px = ptsx * Wf - 0.5f;
        py = ptsy * Wf - 0.5f;
    }
    float mx = logit;
    #pragma unroll
    for (int s = 16; s > 0; s >>= 1) mx = fmaxf(mx, __shfl_xor_sync(0xffffffffu, mx, s));
    float e = (lane < 12) ? expf(logit - mx) : 0.f;
    float ssum = e;
    #pragma unroll
    for (int s = 16; s > 0; s >>= 1) ssum += __shfl_xor_sync(0xffffffffu, ssum, s);
    const float wgt = e / ssum;

    int i00 = 0, i01 = 0, i10 = 0, i11 = 0;
    float w00 = 0.f, w01 = 0.f, w10 = 0.f, w11 = 0.f;
    if (lane < 12) {
        const float x0f = floorf(px), y0f = floorf(py);
        const float fx = px - x0f, fy = py - y0f;
        const int x0 = (int)x0f, y0 = (int)y0f;
        const int x1 = x0 + 1, y1 = y0 + 1;
        const bool vx0 = (unsigned)x0 < (unsigned)W, vx1 = (unsigned)x1 < (unsigned)W;
        const bool vy0 = (unsigned)y0 < (unsigned)W, vy1 = (unsigned)y1 < (unsigned)W;
        const int x0c = min(max(x0, 0), W - 1), x1c = min(max(x1, 0), W - 1);
        const int y0c = min(max(y0, 0), W - 1), y1c = min(max(y1, 0), W - 1);
        i00 = start + y0c * W + x0c;  i01 = start + y0c * W + x1c;
        i10 = start + y1c * W + x0c;  i11 = start + y1c * W + x1c;
        w00 = wgt * (1.f - fx) * (1.f - fy) * (float)(vx0 && vy0);
        w01 = wgt * fx * (1.f - fy) * (float)(vx1 && vy0);
        w10 = wgt * (1.f - fx) * fy * (float)(vx0 && vy1);
        w11 = wgt * fx * fy * (float)(vx1 && vy1);
    }

    const __half* vb = v + (size_t)b * LV * DMODEL + h * HD + lane;
    float acc = 0.f;
    #pragma unroll
    for (int j = 0; j < 12; j++) {
        const int   a00 = __shfl_sync(0xffffffffu, i00, j);
        const int   a01 = __shfl_sync(0xffffffffu, i01, j);
        const int   a10 = __shfl_sync(0xffffffffu, i10, j);
        const int   a11 = __shfl_sync(0xffffffffu, i11, j);
        const float q00 = __shfl_sync(0xffffffffu, w00, j);
        const float q01 = __shfl_sync(0xffffffffu, w01, j);
        const float q10 = __shfl_sync(0xffffffffu, w10, j);
        const float q11 = __shfl_sync(0xffffffffu, w11, j);
        acc += q00 * __half2float(vb[(size_t)a00 * DMODEL]);
        acc += q01 * __half2float(vb[(size_t)a01 * DMODEL]);
        acc += q10 * __half2float(vb[(size_t)a10 * DMODEL]);
        acc += q11 * __half2float(vb[(size_t)a11 * DMODEL]);
    }

    tmp[(size_t)bq * DMODEL + h * HD + lane] = __float2half(acc);
}

// ============================================================================
extern "C" void kernel_launch(void* const* d_in, const int* in_sizes, int n_in,
                              void* d_out, int out_size) {
    const float* query = (const float*)d_in[0];
    const float* rp    = (const float*)d_in[1];
    const float* value = (const float*)d_in[2];
    const float* Wv    = (const float*)d_in[3];
    const float* bv    = (const float*)d_in[4];
    const float* Woff  = (const float*)d_in[5];
    const float* boff  = (const float*)d_in[6];
    const float* Wattn = (const float*)d_in[7];
    const float* battn = (const float*)d_in[8];
    const float* Wout  = (const float*)d_in[9];
    const float* bout  = (const float*)d_in[10];
    float* out = (float*)d_out;

    __half *pv16, *ptmp16, *pwv16, *pwo16;
    float *poff, *pattn;
    cudaGetSymbolAddress((void**)&pv16,   g_v16);
    cudaGetSymbolAddress((void**)&ptmp16, g_tmp16);
    cudaGetSymbolAddress((void**)&pwv16,  g_wv16);
    cudaGetSymbolAddress((void**)&pwo16,  g_wo16);
    cudaGetSymbolAddress((void**)&poff,   g_off);
    cudaGetSymbolAddress((void**)&pattn,  g_attn);

    static bool attr_done = false;
    if (!attr_done) {
        cudaFuncSetAttribute(gemm_fp16<float, __half>,
                             cudaFuncAttributeMaxDynamicSharedMemorySize, SM_TOT_B);
        cudaFuncSetAttribute(gemm_fp16<__half, float>,
                             cudaFuncAttributeMaxDynamicSharedMemorySize, SM_TOT_B);
        attr_done = true;
    }

    // 0) both weights -> fp16 in one launch
    cvt2_fp16<<<128, 256>>>(Wv, pwv16, Wout, pwo16);
    // 1) v = value @ Wv + bv   (fp16 TC, 2 CTAs/SM, coalesced fp16 stores)
    gemm_fp16<float, __half><<<dim3(MV / 128, 2), 256, SM_TOT_B>>>(value, pwv16, bv, pv16, MV);
    // 2+3) offsets + attn logits fused (exact fp32)
    fgemm_qfused<<<dim3(9, BQ / 32), 256>>>(query, Woff, boff, Wattn, battn, poff, pattn);
    // 4) softmax + deformable bilinear sampling -> g_tmp16
    sample_kernel<<<BQ, 256>>>(poff, pattn, rp, pv16, ptmp16);
    // 5) out = tmp @ Wout + bout   (fp16 A, fp32 C, guarded)
    gemm_fp16<__half, float><<<dim3(MT_PAD / 128, 2), 256, SM_TOT_B>>>(ptmp16, pwo16, bout, out, BQ);
}

// round 8
// speedup vs baseline: 1.2224x; 1.0665x over previous
#include <cuda_runtime.h>
#include <cuda_fp16.h>
#include <cstdint>
#include <type_traits>

// ---------------- problem constants ----------------
#define B_      16
#define Q_      300
#define DMODEL  256
#define NHEADS  8
#define HD      32
#define LV      8400          // 80*80 + 40*40 + 20*20
#define BQ      (B_*Q_)       // 4800
#define MV      (B_*LV)       // 134400 rows of value
#define MT_PAD  4864          // 38*128

// ---------------- scratch (device globals; zero-initialized) ----------------
__device__ __half g_v16[MV * DMODEL];        // projected value, fp16
__device__ __half g_tmp16[MT_PAD * DMODEL];  // sampled heads, fp16; rows>=4800 stay 0
__device__ __half g_wv16[DMODEL * DMODEL];   // Wv  in fp16
__device__ __half g_wo16[DMODEL * DMODEL];   // Wout in fp16
__device__ float  g_off[BQ * 192];
__device__ float  g_attn[BQ * 96];

// ---------------- helpers ----------------
__device__ __forceinline__ uint32_t smem_u32(const void* p) {
    uint32_t a;
    asm("{ .reg .u64 t; cvta.to.shared.u64 t, %1; cvt.u32.u64 %0, t; }" : "=r"(a) : "l"(p));
    return a;
}
__device__ __forceinline__ void ldsm_x4(uint32_t* r, uint32_t addr) {
    asm volatile("ldmatrix.sync.aligned.m8n8.x4.shared.b16 {%0,%1,%2,%3}, [%4];"
                 : "=r"(r[0]), "=r"(r[1]), "=r"(r[2]), "=r"(r[3]) : "r"(addr));
}
__device__ __forceinline__ void ldsm_x4_t(uint32_t* r, uint32_t addr) {
    asm volatile("ldmatrix.sync.aligned.m8n8.x4.trans.shared.b16 {%0,%1,%2,%3}, [%4];"
                 : "=r"(r[0]), "=r"(r[1]), "=r"(r[2]), "=r"(r[3]) : "r"(addr));
}
__device__ __forceinline__ void mma16(float* c, const uint32_t* a, const uint32_t* b) {
    asm volatile(
        "mma.sync.aligned.m16n8k16.row.col.f32.f16.f16.f32 "
        "{%0,%1,%2,%3}, {%4,%5,%6,%7}, {%8,%9}, {%0,%1,%2,%3};\n"
        : "+f"(c[0]), "+f"(c[1]), "+f"(c[2]), "+f"(c[3])
        : "r"(a[0]), "r"(a[1]), "r"(a[2]), "r"(a[3]), "r"(b[0]), "r"(b[1]));
}
__device__ __forceinline__ uint32_t packh2(float x, float y) {
    __half2 h = __floats2half2_rn(x, y);
    return *reinterpret_cast<uint32_t*>(&h);
}

// ---------------- fp16 GEMM geometry ----------------
#define BK       32
#define ASTR     40    // halves per A smem row (32 + 8 pad)
#define A_HALVES (128 * ASTR)          // 5120
#define EPI_STR  72
#define EPI_HALVES 1152

// ============================================================================
// fp32 -> fp16 convert for BOTH weight matrices in one launch
// ============================================================================
__global__ void cvt2_fp16(const float* __restrict__ s0, __half* __restrict__ d0,
                          const float* __restrict__ s1, __half* __restrict__ d1) {
    int i = (blockIdx.x * blockDim.x + threadIdx.x) * 4;
    const float* s = (i < DMODEL * DMODEL) ? s0 : s1;
    __half* d      = (i < DMODEL * DMODEL) ? d0 : d1;
    int j = (i < DMODEL * DMODEL) ? i : i - DMODEL * DMODEL;
    float4 v = *reinterpret_cast<const float4*>(s + j);
    uint2 u = make_uint2(packh2(v.x, v.y), packh2(v.z, v.w));
    *reinterpret_cast<uint2*>(d + j) = u;
}

// ============================================================================
// fp16 tensor-core GEMM: C[M x 256] = A[M x 256] @ W16[256 x 256] + bias.
// Block 128(m) x NTILE(n); grid (Mtiles, 256/NTILE). 8 warps as 4(m) x 2(n),
// warp tile 32 x NTILE/2. Double-buffered; next-chunk STS issued between the
// two k16 compute halves to hide it under MMA.
// ============================================================================
template<typename TA, typename TC, int NTILE>
__global__ void __launch_bounds__(256, 2)
gemm_fp16(const TA* __restrict__ A, const __half* __restrict__ W16,
          const float* __restrict__ bias, TC* __restrict__ C, int Mstore) {
    constexpr int WN   = NTILE / 2;          // warp n extent
    constexpr int NI   = WN / 8;             // n8 tiles per warp
    constexpr int NQ   = WN / 16;            // ldsm.x4t per k16
    constexpr int BSTRv = NTILE + 8;         // halves per B smem row
    constexpr int B_HALVESv = 32 * BSTRv;
    constexpr int SM_A0 = 0;
    constexpr int SM_A1 = A_HALVES;
    constexpr int SM_B0 = 2 * A_HALVES;
    constexpr int SM_B1 = 2 * A_HALVES + B_HALVESv;
    constexpr int BNT4 = NTILE / 64;         // uint4 per thread for B fill

    extern __shared__ __half sh[];
    const uint32_t sb = smem_u32(sh);
    const int tid = threadIdx.x, warp = tid >> 5, lane = tid & 31;
    const int wm = warp >> 1, wn = warp & 1;         // 4(m) x 2(n)
    const int g = lane >> 2, tg = lane & 3;
    const int m0 = blockIdx.x * 128;
    const int n0 = blockIdx.y * NTILE;

    const int arow = tid >> 1, ac0 = (tid & 1) * 16;      // A: 16 elems / thread
    const int brow = tid >> 3, bc0 = (tid & 7) * (NTILE / 8);

    float acc[2][NI][4];
    #pragma unroll
    for (int i = 0; i < 2; i++)
        #pragma unroll
        for (int j = 0; j < NI; j++)
            #pragma unroll
            for (int k = 0; k < 4; k++) acc[i][j][k] = 0.f;

    // ---- prologue: fill stage 0 ----
    {
        if constexpr (std::is_same_v<TA, float>) {
            const float* ap = A + (size_t)(m0 + arow) * 256 + ac0;
            #pragma unroll
            for (int i = 0; i < 4; i++) {
                float4 v = *reinterpret_cast<const float4*>(ap + 4 * i);
                uint2 u = make_uint2(packh2(v.x, v.y), packh2(v.z, v.w));
                *reinterpret_cast<uint2*>(&sh[SM_A0 + arow * ASTR + ac0 + 4 * i]) = u;
            }
        } else {
            const __half* ap = A + (size_t)(m0 + arow) * 256 + ac0;
            #pragma unroll
            for (int i = 0; i < 2; i++)
                *reinterpret_cast<uint4*>(&sh[SM_A0 + arow * ASTR + ac0 + 8 * i]) =
                    *reinterpret_cast<const uint4*>(ap + 8 * i);
        }
        const __half* wp = W16 + (size_t)brow * 256 + n0 + bc0;
        #pragma unroll
        for (int i = 0; i < BNT4; i++)
            *reinterpret_cast<uint4*>(&sh[SM_B0 + brow * BSTRv + bc0 + 8 * i]) =
                *reinterpret_cast<const uint4*>(wp + 8 * i);
    }
    __syncthreads();

    const uint32_t a_lrow = (uint32_t)(lane & 15);
    const uint32_t a_kadd = (uint32_t)(lane >> 4) * 8;

    #pragma unroll
    for (int c = 0; c < 8; c++) {
        const int cur = c & 1;
        float4 raf[4]; uint4 rah[2]; uint4 rb[BNT4];
        if (c < 7) {
            const int kc = (c + 1) * BK;
            if constexpr (std::is_same_v<TA, float>) {
                const float* ap = A + (size_t)(m0 + arow) * 256 + kc + ac0;
                #pragma unroll
                for (int i = 0; i < 4; i++)
                    raf[i] = *reinterpret_cast<const float4*>(ap + 4 * i);
            } else {
                const __half* ap = A + (size_t)(m0 + arow) * 256 + kc + ac0;
                #pragma unroll
                for (int i = 0; i < 2; i++)
                    rah[i] = *reinterpret_cast<const uint4*>(ap + 8 * i);
            }
            const __half* wp = W16 + (size_t)(kc + brow) * 256 + n0 + bc0;
            #pragma unroll
            for (int i = 0; i < BNT4; i++)
                rb[i] = *reinterpret_cast<const uint4*>(wp + 8 * i);
        }

        const uint32_t aB = sb + (cur ? SM_A1 : SM_A0) * 2;
        const uint32_t bB = sb + (cur ? SM_B1 : SM_B0) * 2;

        // ---- k16 = 0 ----
        {
            uint32_t af[2][4], bf[NI][2];
            #pragma unroll
            for (int mi = 0; mi < 2; mi++)
                ldsm_x4(af[mi], aB + ((wm * 32 + mi * 16 + a_lrow) * ASTR + a_kadd) * 2);
            #pragma unroll
            for (int nq = 0; nq < NQ; nq++) {
                uint32_t r[4];
                ldsm_x4_t(r, bB + (a_lrow * BSTRv + wn * WN + nq * 16 + a_kadd) * 2);
                bf[2 * nq][0] = r[0]; bf[2 * nq][1] = r[1];
                bf[2 * nq + 1][0] = r[2]; bf[2 * nq + 1][1] = r[3];
            }
            #pragma unroll
            for (int mi = 0; mi < 2; mi++)
                #pragma unroll
                for (int ni = 0; ni < NI; ni++)
                    mma16(acc[mi][ni], af[mi], bf[ni]);
        }

        // ---- STS for next chunk (disjoint buffers) overlapped with k16=1 ----
        if (c < 7) {
            const int nxt = (c + 1) & 1;
            __half* dA = &sh[(nxt ? SM_A1 : SM_A0)];
            __half* dB = &sh[(nxt ? SM_B1 : SM_B0)];
            if constexpr (std::is_same_v<TA, float>) {
                #pragma unroll
                for (int i = 0; i < 4; i++) {
                    uint2 u = make_uint2(packh2(raf[i].x, raf[i].y), packh2(raf[i].z, raf[i].w));
                    *reinterpret_cast<uint2*>(&dA[arow * ASTR + ac0 + 4 * i]) = u;
                }
            } else {
                #pragma unroll
                for (int i = 0; i < 2; i++)
                    *reinterpret_cast<uint4*>(&dA[arow * ASTR + ac0 + 8 * i]) = rah[i];
            }
            #pragma unroll
            for (int i = 0; i < BNT4; i++)
                *reinterpret_cast<uint4*>(&dB[brow * BSTRv + bc0 + 8 * i]) = rb[i];
        }

        // ---- k16 = 1 ----
        {
            uint32_t af[2][4], bf[NI][2];
            #pragma unroll
            for (int mi = 0; mi < 2; mi++)
                ldsm_x4(af[mi], aB + ((wm * 32 + mi * 16 + a_lrow) * ASTR + 16 + a_kadd) * 2);
            #pragma unroll
            for (int nq = 0; nq < NQ; nq++) {
                uint32_t r[4];
                ldsm_x4_t(r, bB + ((16 + a_lrow) * BSTRv + wn * WN + nq * 16 + a_kadd) * 2);
                bf[2 * nq][0] = r[0]; bf[2 * nq][1] = r[1];
                bf[2 * nq + 1][0] = r[2]; bf[2 * nq + 1][1] = r[3];
            }
            #pragma unroll
            for (int mi = 0; mi < 2; mi++)
                #pragma unroll
                for (int ni = 0; ni < NI; ni++)
                    mma16(acc[mi][ni], af[mi], bf[ni]);
        }

        if (c < 7) __syncthreads();
    }

    // ---- epilogue ----
    float2 bb[NI];
    #pragma unroll
    for (int ni = 0; ni < NI; ni++)
        bb[ni] = *reinterpret_cast<const float2*>(&bias[n0 + wn * WN + ni * 8 + 2 * tg]);

    if constexpr (std::is_same_v<TC, __half>) {
        __syncthreads();                   // MMA smem reads done; reuse smem for repack
        __half* buf = &sh[warp * EPI_HALVES];
        #pragma unroll
        for (int mi = 0; mi < 2; mi++) {
            #pragma unroll
            for (int ni = 0; ni < NI; ni++) {
                const int cc = ni * 8 + 2 * tg;
                __half2 lo = __floats2half2_rn(acc[mi][ni][0] + bb[ni].x,
                                               acc[mi][ni][1] + bb[ni].y);
                __half2 hi = __floats2half2_rn(acc[mi][ni][2] + bb[ni].x,
                                               acc[mi][ni][3] + bb[ni].y);
                *reinterpret_cast<__half2*>(&buf[g * EPI_STR + cc]) = lo;
                *reinterpret_cast<__half2*>(&buf[(g + 8) * EPI_STR + cc]) = hi;
            }
            __syncwarp();
            #pragma unroll
            for (int p = 0; p < WN / 16; p++) {
                const int row = p * (256 / WN) + (lane / (WN / 8));
                const int ch  = lane % (WN / 8);
                uint4 v = *reinterpret_cast<const uint4*>(&buf[row * EPI_STR + ch * 8]);
                const int grow = m0 + wm * 32 + mi * 16 + row;
                if (grow < Mstore)
                    *reinterpret_cast<uint4*>(
                        &C[(size_t)grow * 256 + n0 + wn * WN + ch * 8]) = v;
            }
            __syncwarp();
        }
    } else {
        #pragma unroll
        for (int mi = 0; mi < 2; mi++) {
            const int r0 = m0 + wm * 32 + mi * 16 + g;
            const int r1 = r0 + 8;
            #pragma unroll
            for (int ni = 0; ni < NI; ni++) {
                const int cc = n0 + wn * WN + ni * 8 + 2 * tg;
                if (r0 < Mstore)
                    *reinterpret_cast<float2*>(&C[(size_t)r0 * 256 + cc]) =
                        make_float2(acc[mi][ni][0] + bb[ni].x, acc[mi][ni][1] + bb[ni].y);
                if (r1 < Mstore)
                    *reinterpret_cast<float2*>(&C[(size_t)r1 * 256 + cc]) =
                        make_float2(acc[mi][ni][2] + bb[ni].x, acc[mi][ni][3] + bb[ni].y);
            }
        }
    }
}

#define SMEM_G1 ((2 * A_HALVES + 2 * 32 * 136) * 2)   // NTILE=128
#define SMEM_G2 ((2 * A_HALVES + 2 * 32 * 72) * 2)    // NTILE=64

// ============================================================================
// Fused exact fp32 GEMM for offsets + attn logits. Tile 32x32, BK=64.
// grid (9, 150). bx 0..5 -> Woff/g_off, 6..8 -> Wattn/g_attn.
// ============================================================================
__global__ __launch_bounds__(256, 6)
void fgemm_qfused(const float* __restrict__ A,
                  const float* __restrict__ Woff, const float* __restrict__ boff,
                  const float* __restrict__ Wattn, const float* __restrict__ battn,
                  float* __restrict__ Coff, float* __restrict__ Cattn) {
    __shared__ float As[32 * 68];
    __shared__ float Bs[64 * 36];
    const int tid = threadIdx.x;
    const int bx = blockIdx.x;
    const int m0 = blockIdx.y * 32;

    const float* Bm; const float* bias; float* C; int N; int n0;
    if (bx < 6) { Bm = Woff;  bias = boff;  C = Coff;  N = 192; n0 = bx * 32; }
    else        { Bm = Wattn; bias = battn; C = Cattn; N = 96;  n0 = (bx - 6) * 32; }

    const int ty = tid >> 4, tx = tid & 15;          // 2 rows, 2 cols per thread
    const int arow = tid >> 3, acol = (tid & 7) * 4;

    float acc[2][2] = {};
    for (int kc = 0; kc < 256; kc += 64) {
        #pragma unroll
        for (int i = 0; i < 2; i++)
            *reinterpret_cast<float4*>(&As[arow * 68 + acol + 32 * i]) =
                *reinterpret_cast<const float4*>(A + (size_t)(m0 + arow) * 256 + kc + acol + 32 * i);
        #pragma unroll
        for (int i = 0; i < 2; i++)
            *reinterpret_cast<float4*>(&Bs[(arow + 32 * i) * 36 + acol]) =
                *reinterpret_cast<const float4*>(Bm + (size_t)(kc + arow + 32 * i) * N + n0 + acol);
        __syncthreads();
        #pragma unroll
        for (int kk = 0; kk < 64; kk++) {
            const float a0 = As[(ty * 2 + 0) * 68 + kk];
            const float a1 = As[(ty * 2 + 1) * 68 + kk];
            const float2 bv = *reinterpret_cast<const float2*>(&Bs[kk * 36 + tx * 2]);
            acc[0][0] += a0 * bv.x;  acc[0][1] += a0 * bv.y;
            acc[1][0] += a1 * bv.x;  acc[1][1] += a1 * bv.y;
        }
        __syncthreads();
    }
    const float b0 = bias[n0 + tx * 2], b1 = bias[n0 + tx * 2 + 1];
    #pragma unroll
    for (int i = 0; i < 2; i++) {
        float2 v = make_float2(acc[i][0] + b0, acc[i][1] + b1);
        *reinterpret_cast<float2*>(&C[(size_t)(m0 + ty * 2 + i) * N + n0 + tx * 2]) = v;
    }
}

// ============================================================================
// Deformable sampling: 2 heads per warp (16 lanes x __half2 each).
// Grid BQ/2; block 256 = 8 warps = 16 half-warps = 2 queries x 8 heads.
// ============================================================================
__global__ __launch_bounds__(256)
void sample_kernel(const float* __restrict__ off, const float* __restrict__ attn,
                   const float* __restrict__ rp, const __half* __restrict__ v,
                   __half* __restrict__ tmp) {
    const int warp = threadIdx.x >> 5;
    const int lane = threadIdx.x & 31;
    const int hw   = warp * 2 + (lane >> 4);   // 0..15
    const int l16  = lane & 15;
    const int bq   = blockIdx.x * 2 + (hw >> 3);
    const int h    = hw & 7;
    const int b    = bq / Q_;

    const float refx = rp[bq * 4 + 0];
    const float refy = rp[bq * 4 + 1];

    float logit = -1e30f, px = 0.f, py = 0.f;
    int W = 1, start = 0;
    if (l16 < 12) {
        logit = attn[bq * 96 + h * 12 + l16];
        const float ox = off[bq * 192 + h * 24 + l16 * 2 + 0];
        const float oy = off[bq * 192 + h * 24 + l16 * 2 + 1];
        const int lvl = l16 >> 2;
        W     = (lvl == 0) ? 80 : ((lvl == 1) ? 40 : 20);
        start = (lvl == 0) ? 0 : ((lvl == 1) ? 6400 : 8000);
        const float Wf = (float)W;
        const float ptsx = fminf(fmaxf(refx + ox, 0.f), 1.f);
        const float ptsy = fminf(fmaxf(refy + oy, 0.f), 1.f);
        px = ptsx * Wf - 0.5f;
        py = ptsy * Wf - 0.5f;
    }
    // softmax over the 12 valid lanes of this 16-lane segment
    float mx = logit;
    #pragma unroll
    for (int s = 8; s > 0; s >>= 1) mx = fmaxf(mx, __shfl_xor_sync(0xffffffffu, mx, s, 16));
    float e = (l16 < 12) ? expf(logit - mx) : 0.f;
    float ssum = e;
    #pragma unroll
    for (int s = 8; s > 0; s >>= 1) ssum += __shfl_xor_sync(0xffffffffu, ssum, s, 16);
    const float wgt = e / ssum;

    // owner-lane corner precompute
    int i00 = 0, i01 = 0, i10 = 0, i11 = 0;
    float w00 = 0.f, w01 = 0.f, w10 = 0.f, w11 = 0.f;
    if (l16 < 12) {
        const float x0f = floorf(px), y0f = floorf(py);
        const float fx = px - x0f, fy = py - y0f;
        const int x0 = (int)x0f, y0 = (int)y0f;
        const int x1 = x0 + 1, y1 = y0 + 1;
        const bool vx0 = (unsigned)x0 < (unsigned)W, vx1 = (unsigned)x1 < (unsigned)W;
        const bool vy0 = (unsigned)y0 < (unsigned)W, vy1 = (unsigned)y1 < (unsigned)W;
        const int x0c = min(max(x0, 0), W - 1), x1c = min(max(x1, 0), W - 1);
        const int y0c = min(max(y0, 0), W - 1), y1c = min(max(y1, 0), W - 1);
        i00 = start + y0c * W + x0c;  i01 = start + y0c * W + x1c;
        i10 = start + y1c * W + x0c;  i11 = start + y1c * W + x1c;
        w00 = wgt * (1.f - fx) * (1.f - fy) * (float)(vx0 && vy0);
        w01 = wgt * fx * (1.f - fy) * (float)(vx1 && vy0);
        w10 = wgt * (1.f - fx) * fy * (float)(vx0 && vy1);
        w11 = wgt * fx * fy * (float)(vx1 && vy1);
    }

    // each lane covers dims {2*l16, 2*l16+1} of this head's 32-dim slice
    const __half2* vp = reinterpret_cast<const __half2*>(
        v + (size_t)b * LV * DMODEL + h * HD) + l16;   // row stride = 128 half2
    float ax = 0.f, ay = 0.f;
    #pragma unroll
    for (int j = 0; j < 12; j++) {
        const int   a00 = __shfl_sync(0xffffffffu, i00, j, 16);
        const int   a01 = __shfl_sync(0xffffffffu, i01, j, 16);
        const int   a10 = __shfl_sync(0xffffffffu, i10, j, 16);
        const int   a11 = __shfl_sync(0xffffffffu, i11, j, 16);
        const float q00 = __shfl_sync(0xffffffffu, w00, j, 16);
        const float q01 = __shfl_sync(0xffffffffu, w01, j, 16);
        const float q10 = __shfl_sync(0xffffffffu, w10, j, 16);
        const float q11 = __shfl_sync(0xffffffffu, w11, j, 16);
        float2 f0 = __half22float2(vp[(size_t)a00 * 128]);
        float2 f1 = __half22float2(vp[(size_t)a01 * 128]);
        float2 f2 = __half22float2(vp[(size_t)a10 * 128]);
        float2 f3 = __half22float2(vp[(size_t)a11 * 128]);
        ax += q00 * f0.x + q01 * f1.x + q10 * f2.x + q11 * f3.x;
        ay += q00 * f0.y + q01 * f1.y + q10 * f2.y + q11 * f3.y;
    }

    __half2* tp = reinterpret_cast<__half2*>(tmp + (size_t)bq * DMODEL + h * HD) + l16;
    *tp = __floats2half2_rn(ax, ay);
}

// ============================================================================
extern "C" void kernel_launch(void* const* d_in, const int* in_sizes, int n_in,
                              void* d_out, int out_size) {
    const float* query = (const float*)d_in[0];
    const float* rp    = (const float*)d_in[1];
    const float* value = (const float*)d_in[2];
    const float* Wv    = (const float*)d_in[3];
    const float* bv    = (const float*)d_in[4];
    const float* Woff  = (const float*)d_in[5];
    const float* boff  = (const float*)d_in[6];
    const float* Wattn = (const float*)d_in[7];
    const float* battn = (const float*)d_in[8];
    const float* Wout  = (const float*)d_in[9];
    const float* bout  = (const float*)d_in[10];
    float* out = (float*)d_out;

    __half *pv16, *ptmp16, *pwv16, *pwo16;
    float *poff, *pattn;
    cudaGetSymbolAddress((void**)&pv16,   g_v16);
    cudaGetSymbolAddress((void**)&ptmp16, g_tmp16);
    cudaGetSymbolAddress((void**)&pwv16,  g_wv16);
    cudaGetSymbolAddress((void**)&pwo16,  g_wo16);
    cudaGetSymbolAddress((void**)&poff,   g_off);
    cudaGetSymbolAddress((void**)&pattn,  g_attn);

    static bool attr_done = false;
    if (!attr_done) {
        cudaFuncSetAttribute(gemm_fp16<float, __half, 128>,
                             cudaFuncAttributeMaxDynamicSharedMemorySize, SMEM_G1);
        cudaFuncSetAttribute(gemm_fp16<__half, float, 64>,
                             cudaFuncAttributeMaxDynamicSharedMemorySize, SMEM_G2);
        attr_done = true;
    }

    // 0) both weights -> fp16 in one launch
    cvt2_fp16<<<128, 256>>>(Wv, pwv16, Wout, pwo16);
    // 1) v = value @ Wv + bv   (fp16 TC, 2 CTAs/SM, coalesced fp16 stores)
    gemm_fp16<float, __half, 128><<<dim3(MV / 128, 2), 256, SMEM_G1>>>(value, pwv16, bv, pv16, MV);
    // 2+3) offsets + attn logits fused (exact fp32, BK=64)
    fgemm_qfused<<<dim3(9, BQ / 32), 256>>>(query, Woff, boff, Wattn, battn, poff, pattn);
    // 4) softmax + deformable bilinear sampling (2 heads/warp, half2 lanes)
    sample_kernel<<<BQ / 2, 256>>>(poff, pattn, rp, pv16, ptmp16);
    // 5) out = tmp @ Wout + bout   (fp16 A, fp32 C, N-tile 64 -> 152 CTAs)
    gemm_fp16<__half, float, 64><<<dim3(MT_PAD / 128, 4), 256, SMEM_G2>>>(ptmp16, pwo16, bout, out, BQ);
}